// round 3
// baseline (speedup 1.0000x reference)
#include <cuda_runtime.h>
#include <math.h>

#define BATCH   2
#define SEQLEN  2048
#define DMODEL  1024
#define NHEADS  16
#define DHEAD   64
#define FFDIM   4096
#define BL      (BATCH*SEQLEN)          // 4096
#define NPER    (SEQLEN*DMODEL)         // per-batch layernorm size

// ---------------- scratch (static device globals; no allocation allowed) ----
__device__ float g_q   [BL*DMODEL];
__device__ float g_k   [BL*DMODEL];
__device__ float g_v   [BL*DMODEL];
__device__ float g_attn[BL*DMODEL];
__device__ float g_h   [BL*DMODEL];
__device__ float g_ff1 [BL*FFDIM];
__device__ float g_ff2 [BL*DMODEL];
__device__ double g_part[BATCH*256*2];
__device__ float  g_stats[BATCH*2];

// ---------------------------------------------------------------- SGEMM ----
// C[M,N] = A[M,K] @ W[K,N] + bias (+optional relu). 128x128x8 tile, 8x8/thread.
#define GBM 128
#define GBN 128
#define GBK 8

__global__ __launch_bounds__(256) void sgemm_bias(
    const float* __restrict__ A, const float* __restrict__ W,
    const float* __restrict__ bias, float* __restrict__ C,
    int M, int N, int K, int relu)
{
    __shared__ float As[GBK][GBM];
    __shared__ float Ws[GBK][GBN];

    const int tid = threadIdx.x;
    const int tx = tid & 15, ty = tid >> 4;
    const int bx = blockIdx.x, by = blockIdx.y;

    const int arow = tid >> 1, acol = (tid & 1) * 4;     // A: 128 rows x 8 cols
    const int wrow = tid >> 5, wcol = (tid & 31) * 4;    // W: 8 rows x 128 cols

    const float* Aptr = A + (size_t)(by*GBM + arow)*K + acol;
    const float* Wptr = W + (size_t)wrow*N + bx*GBN + wcol;

    float acc[8][8];
    #pragma unroll
    for (int i = 0; i < 8; i++)
        #pragma unroll
        for (int j = 0; j < 8; j++) acc[i][j] = 0.f;

    #pragma unroll 1
    for (int k0 = 0; k0 < K; k0 += GBK) {
        float4 av = *(const float4*)Aptr;
        As[acol+0][arow] = av.x;
        As[acol+1][arow] = av.y;
        As[acol+2][arow] = av.z;
        As[acol+3][arow] = av.w;
        *(float4*)&Ws[wrow][wcol] = *(const float4*)Wptr;
        __syncthreads();

        #pragma unroll
        for (int kk = 0; kk < GBK; kk++) {
            float a[8], b[8];
            *(float4*)&a[0] = *(float4*)&As[kk][ty*4];
            *(float4*)&a[4] = *(float4*)&As[kk][64 + ty*4];
            *(float4*)&b[0] = *(float4*)&Ws[kk][tx*4];
            *(float4*)&b[4] = *(float4*)&Ws[kk][64 + tx*4];
            #pragma unroll
            for (int i = 0; i < 8; i++)
                #pragma unroll
                for (int j = 0; j < 8; j++)
                    acc[i][j] = fmaf(a[i], b[j], acc[i][j]);
        }
        __syncthreads();
        Aptr += GBK;
        Wptr += (size_t)GBK*N;
    }

    const int colBase = bx*GBN + tx*4;
    const float4 b0 = *(const float4*)(bias + colBase);
    const float4 b1 = *(const float4*)(bias + colBase + 64);
    #pragma unroll
    for (int i = 0; i < 8; i++) {
        int row = by*GBM + ((i < 4) ? (ty*4 + i) : (64 + ty*4 + i - 4));
        float4 c0, c1;
        c0.x = acc[i][0] + b0.x; c0.y = acc[i][1] + b0.y;
        c0.z = acc[i][2] + b0.z; c0.w = acc[i][3] + b0.w;
        c1.x = acc[i][4] + b1.x; c1.y = acc[i][5] + b1.y;
        c1.z = acc[i][6] + b1.z; c1.w = acc[i][7] + b1.w;
        if (relu) {
            c0.x = fmaxf(c0.x, 0.f); c0.y = fmaxf(c0.y, 0.f);
            c0.z = fmaxf(c0.z, 0.f); c0.w = fmaxf(c0.w, 0.f);
            c1.x = fmaxf(c1.x, 0.f); c1.y = fmaxf(c1.y, 0.f);
            c1.z = fmaxf(c1.z, 0.f); c1.w = fmaxf(c1.w, 0.f);
        }
        *(float4*)(C + (size_t)row*N + colBase)      = c0;
        *(float4*)(C + (size_t)row*N + colBase + 64) = c1;
    }
}

// ------------------------------------------------------- flash attention ----
// One block: 64 query rows of one (batch, head). Online softmax over K tiles
// of 64. 256 threads; thread (ty,tx) owns S rows 4ty..+3 x S cols 4tx..+3 and
// O rows 4ty..+3 x dims 4tx..+3. Smem: QsT + (KsT aliased with Ps) + Vs = 48KB.
__global__ __launch_bounds__(256) void flash_attn_kernel(
    const float* __restrict__ Q, const float* __restrict__ K,
    const float* __restrict__ V, float* __restrict__ O, int L)
{
    __shared__ float QsT[64*64];   // QsT[kk][qrow]
    __shared__ float KP [64*64];   // phase 1: KsT[kk][krow]; phase 2: Ps[qrow][krow]
    __shared__ float Vs [64*64];   // Vs[krow][dim]

    const int tid = threadIdx.x;
    const int tx = tid & 15, ty = tid >> 4;
    const int b = blockIdx.z, h = blockIdx.y, q0 = blockIdx.x * 64;

    const size_t base = ((size_t)b * L) * DMODEL + h * DHEAD;

    const int lr = tid >> 2;            // 0..63 loader row
    const int lc = (tid & 3) * 16;      // loader col segment

    {   // load Q tile, transposed
        const float* qp = Q + base + (size_t)(q0 + lr) * DMODEL + lc;
        #pragma unroll
        for (int j = 0; j < 4; j++) {
            float4 v = *(const float4*)(qp + 4*j);
            QsT[(lc+4*j+0)*64 + lr] = v.x;
            QsT[(lc+4*j+1)*64 + lr] = v.y;
            QsT[(lc+4*j+2)*64 + lr] = v.z;
            QsT[(lc+4*j+3)*64 + lr] = v.w;
        }
    }

    float m[4], l[4], acc[4][4];
    #pragma unroll
    for (int i = 0; i < 4; i++) {
        m[i] = -INFINITY; l[i] = 0.f;
        #pragma unroll
        for (int j = 0; j < 4; j++) acc[i][j] = 0.f;
    }

    const int ntiles = L / 64;
    for (int kt = 0; kt < ntiles; kt++) {
        __syncthreads();   // previous iteration's consumers done
        {   // load K (transposed) and V tiles
            const float* kp = K + base + (size_t)(kt*64 + lr) * DMODEL + lc;
            const float* vp = V + base + (size_t)(kt*64 + lr) * DMODEL + lc;
            #pragma unroll
            for (int j = 0; j < 4; j++) {
                float4 kv = *(const float4*)(kp + 4*j);
                KP[(lc+4*j+0)*64 + lr] = kv.x;
                KP[(lc+4*j+1)*64 + lr] = kv.y;
                KP[(lc+4*j+2)*64 + lr] = kv.z;
                KP[(lc+4*j+3)*64 + lr] = kv.w;
                *(float4*)&Vs[lr*64 + lc + 4*j] = *(const float4*)(vp + 4*j);
            }
        }
        __syncthreads();

        // S = Q @ K^T  (per-thread 4x4)
        float s[4][4];
        #pragma unroll
        for (int i = 0; i < 4; i++)
            #pragma unroll
            for (int j = 0; j < 4; j++) s[i][j] = 0.f;

        #pragma unroll 8
        for (int kk = 0; kk < 64; kk++) {
            float4 qv = *(const float4*)&QsT[kk*64 + 4*ty];
            float4 kv = *(const float4*)&KP [kk*64 + 4*tx];
            s[0][0] = fmaf(qv.x, kv.x, s[0][0]); s[0][1] = fmaf(qv.x, kv.y, s[0][1]);
            s[0][2] = fmaf(qv.x, kv.z, s[0][2]); s[0][3] = fmaf(qv.x, kv.w, s[0][3]);
            s[1][0] = fmaf(qv.y, kv.x, s[1][0]); s[1][1] = fmaf(qv.y, kv.y, s[1][1]);
            s[1][2] = fmaf(qv.y, kv.z, s[1][2]); s[1][3] = fmaf(qv.y, kv.w, s[1][3]);
            s[2][0] = fmaf(qv.z, kv.x, s[2][0]); s[2][1] = fmaf(qv.z, kv.y, s[2][1]);
            s[2][2] = fmaf(qv.z, kv.z, s[2][2]); s[2][3] = fmaf(qv.z, kv.w, s[2][3]);
            s[3][0] = fmaf(qv.w, kv.x, s[3][0]); s[3][1] = fmaf(qv.w, kv.y, s[3][1]);
            s[3][2] = fmaf(qv.w, kv.z, s[3][2]); s[3][3] = fmaf(qv.w, kv.w, s[3][3]);
        }

        __syncthreads();   // all KsT reads done; KP becomes Ps

        // online softmax (row stats shared across the 16 tx lanes via shfl)
        const float scale = 0.125f;   // 1/sqrt(64)
        #pragma unroll
        for (int i = 0; i < 4; i++) {
            float a0 = s[i][0]*scale, a1 = s[i][1]*scale;
            float a2 = s[i][2]*scale, a3 = s[i][3]*scale;
            float rm = fmaxf(fmaxf(a0, a1), fmaxf(a2, a3));
            rm = fmaxf(rm, __shfl_xor_sync(0xffffffffu, rm, 1));
            rm = fmaxf(rm, __shfl_xor_sync(0xffffffffu, rm, 2));
            rm = fmaxf(rm, __shfl_xor_sync(0xffffffffu, rm, 4));
            rm = fmaxf(rm, __shfl_xor_sync(0xffffffffu, rm, 8));
            float mnew = fmaxf(m[i], rm);
            float corr = __expf(m[i] - mnew);
            float p0 = __expf(a0 - mnew), p1 = __expf(a1 - mnew);
            float p2 = __expf(a2 - mnew), p3 = __expf(a3 - mnew);
            float rs = (p0 + p1) + (p2 + p3);
            rs += __shfl_xor_sync(0xffffffffu, rs, 1);
            rs += __shfl_xor_sync(0xffffffffu, rs, 2);
            rs += __shfl_xor_sync(0xffffffffu, rs, 4);
            rs += __shfl_xor_sync(0xffffffffu, rs, 8);
            l[i] = l[i]*corr + rs;
            m[i] = mnew;
            acc[i][0] *= corr; acc[i][1] *= corr;
            acc[i][2] *= corr; acc[i][3] *= corr;
            *(float4*)&KP[(4*ty + i)*64 + 4*tx] = make_float4(p0, p1, p2, p3);
        }
        __syncthreads();   // Ps visible

        // O += P @ V
        #pragma unroll 8
        for (int key = 0; key < 64; key++) {
            float4 vv = *(const float4*)&Vs[key*64 + 4*tx];
            #pragma unroll
            for (int i = 0; i < 4; i++) {
                float pv = KP[(4*ty + i)*64 + key];
                acc[i][0] = fmaf(pv, vv.x, acc[i][0]);
                acc[i][1] = fmaf(pv, vv.y, acc[i][1]);
                acc[i][2] = fmaf(pv, vv.z, acc[i][2]);
                acc[i][3] = fmaf(pv, vv.w, acc[i][3]);
            }
        }
    }

    #pragma unroll
    for (int i = 0; i < 4; i++) {
        float inv = 1.0f / l[i];
        float4 o = make_float4(acc[i][0]*inv, acc[i][1]*inv,
                               acc[i][2]*inv, acc[i][3]*inv);
        *(float4*)(O + base + (size_t)(q0 + 4*ty + i)*DMODEL + 4*tx) = o;
    }
}

// ------------------------------------------------------------ layernorm ----
// LN over (L,C) jointly per batch: deterministic 2-stage reduction, then apply.
__global__ __launch_bounds__(256) void ln_reduce(
    const float* __restrict__ a, const float* __restrict__ b,
    double* __restrict__ part)
{
    const int batch = blockIdx.y;
    const float* pa = a + (size_t)batch * NPER;
    const float* pb = b + (size_t)batch * NPER;
    double s = 0.0, ss = 0.0;
    for (int i = blockIdx.x*blockDim.x + threadIdx.x; i < NPER;
         i += gridDim.x*blockDim.x) {
        float z = pa[i] + pb[i];
        s += (double)z;
        ss += (double)z * (double)z;
    }
    __shared__ double sh[512];
    int tid = threadIdx.x;
    sh[tid] = s; sh[256 + tid] = ss;
    __syncthreads();
    for (int st = 128; st > 0; st >>= 1) {
        if (tid < st) { sh[tid] += sh[tid+st]; sh[256+tid] += sh[256+tid+st]; }
        __syncthreads();
    }
    if (tid == 0) {
        part[(batch*256 + blockIdx.x)*2 + 0] = sh[0];
        part[(batch*256 + blockIdx.x)*2 + 1] = sh[256];
    }
}

__global__ __launch_bounds__(256) void ln_stats(
    const double* __restrict__ part, float* __restrict__ stats)
{
    const int batch = blockIdx.x;
    int tid = threadIdx.x;
    __shared__ double sh[512];
    sh[tid]       = part[(batch*256 + tid)*2 + 0];
    sh[256 + tid] = part[(batch*256 + tid)*2 + 1];
    __syncthreads();
    for (int st = 128; st > 0; st >>= 1) {
        if (tid < st) { sh[tid] += sh[tid+st]; sh[256+tid] += sh[256+tid+st]; }
        __syncthreads();
    }
    if (tid == 0) {
        double mean = sh[0] / (double)NPER;
        double var  = sh[256] / (double)NPER - mean*mean + 1e-5;
        stats[batch*2 + 0] = (float)mean;
        stats[batch*2 + 1] = (float)(1.0 / sqrt(var));
    }
}

__global__ __launch_bounds__(256) void ln_apply(
    const float* __restrict__ a, const float* __restrict__ b,
    const float* __restrict__ stats, float* __restrict__ out)
{
    const int batch = blockIdx.y;
    const float mean = stats[batch*2 + 0];
    const float inv  = stats[batch*2 + 1];
    size_t off = (size_t)batch * NPER + (size_t)(blockIdx.x*blockDim.x + threadIdx.x)*4;
    float4 va = *(const float4*)(a + off);
    float4 vb = *(const float4*)(b + off);
    float4 o;
    o.x = (va.x + vb.x - mean) * inv;
    o.y = (va.y + vb.y - mean) * inv;
    o.z = (va.z + vb.z - mean) * inv;
    o.w = (va.w + vb.w - mean) * inv;
    *(float4*)(out + off) = o;
}

// -------------------------------------------------------------- launch -----
extern "C" void kernel_launch(void* const* d_in, const int* in_sizes, int n_in,
                              void* d_out, int out_size)
{
    const float* x  = (const float*)d_in[0];
    const float* wq = (const float*)d_in[1];
    const float* bq = (const float*)d_in[2];
    const float* wk = (const float*)d_in[3];
    const float* bk = (const float*)d_in[4];
    const float* wv = (const float*)d_in[5];
    const float* bv = (const float*)d_in[6];
    const float* w1 = (const float*)d_in[7];
    const float* b1 = (const float*)d_in[8];
    const float* w2 = (const float*)d_in[9];
    const float* b2 = (const float*)d_in[10];
    float* out = (float*)d_out;

    float *q, *k, *v, *attn, *h, *ff1, *ff2, *stats;
    double* part;
    cudaGetSymbolAddress((void**)&q,    g_q);
    cudaGetSymbolAddress((void**)&k,    g_k);
    cudaGetSymbolAddress((void**)&v,    g_v);
    cudaGetSymbolAddress((void**)&attn, g_attn);
    cudaGetSymbolAddress((void**)&h,    g_h);
    cudaGetSymbolAddress((void**)&ff1,  g_ff1);
    cudaGetSymbolAddress((void**)&ff2,  g_ff2);
    cudaGetSymbolAddress((void**)&part, g_part);
    cudaGetSymbolAddress((void**)&stats, g_stats);

    // QKV projections
    dim3 gqkv(DMODEL/GBN, BL/GBM);
    sgemm_bias<<<gqkv, 256>>>(x, wq, bq, q, BL, DMODEL, DMODEL, 0);
    sgemm_bias<<<gqkv, 256>>>(x, wk, bk, k, BL, DMODEL, DMODEL, 0);
    sgemm_bias<<<gqkv, 256>>>(x, wv, bv, v, BL, DMODEL, DMODEL, 0);

    // attention
    flash_attn_kernel<<<dim3(SEQLEN/64, NHEADS, BATCH), 256>>>(q, k, v, attn, SEQLEN);

    // residual + LN1 -> h
    ln_reduce<<<dim3(256, BATCH), 256>>>(x, attn, part);
    ln_stats <<<BATCH, 256>>>(part, stats);
    ln_apply <<<dim3(NPER/1024, BATCH), 256>>>(x, attn, stats, h);

    // FFN
    sgemm_bias<<<dim3(FFDIM/GBN,  BL/GBM), 256>>>(h,   w1, b1, ff1, BL, FFDIM,  DMODEL, 1);
    sgemm_bias<<<dim3(DMODEL/GBN, BL/GBM), 256>>>(ff1, w2, b2, ff2, BL, DMODEL, FFDIM,  0);

    // residual + LN2 -> out
    ln_reduce<<<dim3(256, BATCH), 256>>>(h, ff2, part);
    ln_stats <<<BATCH, 256>>>(part, stats);
    ln_apply <<<dim3(NPER/1024, BATCH), 256>>>(h, ff2, stats, out);
}

// round 7
// speedup vs baseline: 1.7675x; 1.7675x over previous
#include <cuda_runtime.h>
#include <cstdint>
#include <math.h>

#define BATCH   2
#define SEQLEN  2048
#define DMODEL  1024
#define NHEADS  16
#define DHEAD   64
#define FFDIM   4096
#define BL      (BATCH*SEQLEN)          // 4096
#define NPER    (SEQLEN*DMODEL)        // per-batch layernorm size

// ---------------- scratch (static device globals; no allocation allowed) ----
__device__ float g_q   [BL*DMODEL];
__device__ float g_k   [BL*DMODEL];
__device__ float g_v   [BL*DMODEL];
__device__ float g_attn[BL*DMODEL];
__device__ float g_h   [BL*DMODEL];
__device__ float g_ff1 [BL*FFDIM];
__device__ float g_ff2 [BL*DMODEL];
__device__ double g_part[BATCH*256*2];
__device__ float  g_stats[BATCH*2];

// ------------------------------------------------------------- tf32 GEMM ----
// C[M,N] = A[M,K] @ W[K,N] + bias (+relu). Tensor cores via mma.sync tf32.
// Block tile 128x128, K-chunk 16, double-buffered smem. 8 warps; each warp
// owns a 64x32 tile = 4x4 grid of m16n8k8 fragments.
#define TBM 128
#define TBN 128
#define TBK 16
#define ASTRIDE 20     // A smem [m][k] stride: (20*q + r) mod 32 covers all banks
#define WSTRIDE 136    // W smem [k][n] stride: bank = 8r + q, conflict-free

__device__ __forceinline__ uint32_t f2tf32(float x) {
    uint32_t u;
    asm("cvt.rna.tf32.f32 %0, %1;" : "=r"(u) : "f"(x));
    return u;
}

__device__ __forceinline__ void mma_tf32(float* c, const uint32_t* a, const uint32_t* b) {
    asm volatile(
        "mma.sync.aligned.m16n8k8.row.col.f32.tf32.tf32.f32 "
        "{%0,%1,%2,%3}, {%4,%5,%6,%7}, {%8,%9}, {%0,%1,%2,%3};"
        : "+f"(c[0]), "+f"(c[1]), "+f"(c[2]), "+f"(c[3])
        : "r"(a[0]), "r"(a[1]), "r"(a[2]), "r"(a[3]), "r"(b[0]), "r"(b[1]));
}

__global__ __launch_bounds__(256) void tf32_gemm_bias(
    const float* __restrict__ A, const float* __restrict__ W,
    const float* __restrict__ bias, float* __restrict__ C,
    int M, int N, int K, int relu)
{
    __shared__ uint32_t As[2][TBM*ASTRIDE];   // [m][k] tf32 bits
    __shared__ uint32_t Ws[2][TBK*WSTRIDE];   // [k][n] tf32 bits

    const int tid  = threadIdx.x;
    const int lane = tid & 31;
    const int warp = tid >> 5;
    const int q = lane >> 2, r = lane & 3;         // groupID / threadID-in-group
    const int wr = warp >> 2, wc = warp & 3;       // warp row (0-1) / col (0-3)
    const int bm = blockIdx.y * TBM, bn = blockIdx.x * TBN;

    // global load mapping
    const int arow = tid >> 2;            // 0..63 (2nd float4 at +64 rows)
    const int akc  = (tid & 3) * 4;       // k offset 0/4/8/12
    const int wrow = tid >> 5;            // 0..7  (2nd float4 at +8 rows)
    const int wcol = (tid & 31) * 4;      // 0..124

    const float* Ag = A + (size_t)(bm + arow) * K + akc;
    const float* Wg = W + (size_t)wrow * N + bn + wcol;

    float acc[4][4][4];
    #pragma unroll
    for (int i = 0; i < 4; i++)
        #pragma unroll
        for (int j = 0; j < 4; j++)
            #pragma unroll
            for (int e = 0; e < 4; e++) acc[i][j][e] = 0.f;

    float4 ra0, ra1, rw0, rw1;

    // prologue: chunk 0 -> buffer 0
    ra0 = *(const float4*)Ag;
    ra1 = *(const float4*)(Ag + (size_t)64 * K);
    rw0 = *(const float4*)Wg;
    rw1 = *(const float4*)(Wg + (size_t)8 * N);
    Ag += TBK;
    Wg += (size_t)TBK * N;
    {
        uint4 pa0 = make_uint4(f2tf32(ra0.x), f2tf32(ra0.y), f2tf32(ra0.z), f2tf32(ra0.w));
        uint4 pa1 = make_uint4(f2tf32(ra1.x), f2tf32(ra1.y), f2tf32(ra1.z), f2tf32(ra1.w));
        uint4 pw0 = make_uint4(f2tf32(rw0.x), f2tf32(rw0.y), f2tf32(rw0.z), f2tf32(rw0.w));
        uint4 pw1 = make_uint4(f2tf32(rw1.x), f2tf32(rw1.y), f2tf32(rw1.z), f2tf32(rw1.w));
        *(uint4*)&As[0][arow*ASTRIDE + akc]        = pa0;
        *(uint4*)&As[0][(arow + 64)*ASTRIDE + akc] = pa1;
        *(uint4*)&Ws[0][wrow*WSTRIDE + wcol]       = pw0;
        *(uint4*)&Ws[0][(wrow + 8)*WSTRIDE + wcol] = pw1;
    }
    __syncthreads();

    const int nchunk = K / TBK;
    #pragma unroll 1
    for (int c = 0; c < nchunk; c++) {
        const int cur = c & 1;
        const bool has_next = (c + 1 < nchunk);

        if (has_next) {
            ra0 = *(const float4*)Ag;
            ra1 = *(const float4*)(Ag + (size_t)64 * K);
            rw0 = *(const float4*)Wg;
            rw1 = *(const float4*)(Wg + (size_t)8 * N);
            Ag += TBK;
            Wg += (size_t)TBK * N;
        }

        // two k8 steps from current buffer
        #pragma unroll
        for (int k8 = 0; k8 < TBK; k8 += 8) {
            uint32_t af[4][4], bf[4][2];
            #pragma unroll
            for (int tm = 0; tm < 4; tm++) {
                const int m = wr*64 + tm*16 + q;
                af[tm][0] = As[cur][m*ASTRIDE + k8 + r];
                af[tm][1] = As[cur][(m + 8)*ASTRIDE + k8 + r];
                af[tm][2] = As[cur][m*ASTRIDE + k8 + r + 4];
                af[tm][3] = As[cur][(m + 8)*ASTRIDE + k8 + r + 4];
            }
            #pragma unroll
            for (int tn = 0; tn < 4; tn++) {
                const int n = wc*32 + tn*8 + q;
                bf[tn][0] = Ws[cur][(k8 + r)*WSTRIDE + n];
                bf[tn][1] = Ws[cur][(k8 + r + 4)*WSTRIDE + n];
            }
            #pragma unroll
            for (int tm = 0; tm < 4; tm++)
                #pragma unroll
                for (int tn = 0; tn < 4; tn++)
                    mma_tf32(acc[tm][tn], af[tm], bf[tn]);
        }

        if (has_next) {
            const int nxt = cur ^ 1;
            uint4 pa0 = make_uint4(f2tf32(ra0.x), f2tf32(ra0.y), f2tf32(ra0.z), f2tf32(ra0.w));
            uint4 pa1 = make_uint4(f2tf32(ra1.x), f2tf32(ra1.y), f2tf32(ra1.z), f2tf32(ra1.w));
            uint4 pw0 = make_uint4(f2tf32(rw0.x), f2tf32(rw0.y), f2tf32(rw0.z), f2tf32(rw0.w));
            uint4 pw1 = make_uint4(f2tf32(rw1.x), f2tf32(rw1.y), f2tf32(rw1.z), f2tf32(rw1.w));
            *(uint4*)&As[nxt][arow*ASTRIDE + akc]        = pa0;
            *(uint4*)&As[nxt][(arow + 64)*ASTRIDE + akc] = pa1;
            *(uint4*)&Ws[nxt][wrow*WSTRIDE + wcol]       = pw0;
            *(uint4*)&Ws[nxt][(wrow + 8)*WSTRIDE + wcol] = pw1;
        }
        __syncthreads();
    }

    // epilogue: bias (+relu), fragment layout -> global
    #pragma unroll
    for (int tm = 0; tm < 4; tm++) {
        const int row = bm + wr*64 + tm*16 + q;
        #pragma unroll
        for (int tn = 0; tn < 4; tn++) {
            const int col = bn + wc*32 + tn*8 + 2*r;
            const float2 bv = *(const float2*)(bias + col);
            float2 c01, c23;
            c01.x = acc[tm][tn][0] + bv.x; c01.y = acc[tm][tn][1] + bv.y;
            c23.x = acc[tm][tn][2] + bv.x; c23.y = acc[tm][tn][3] + bv.y;
            if (relu) {
                c01.x = fmaxf(c01.x, 0.f); c01.y = fmaxf(c01.y, 0.f);
                c23.x = fmaxf(c23.x, 0.f); c23.y = fmaxf(c23.y, 0.f);
            }
            *(float2*)(C + (size_t)row*N + col)       = c01;
            *(float2*)(C + (size_t)(row + 8)*N + col) = c23;
        }
    }
}

// ------------------------------------------------------- flash attention ----
// One block: 64 query rows of one (batch, head). Online softmax over K tiles
// of 64. 256 threads; thread (ty,tx) owns S rows 4ty..+3 x S cols 4tx..+3 and
// O rows 4ty..+3 x dims 4tx..+3. Smem: QsT + (KsT aliased with Ps) + Vs = 48KB.
__global__ __launch_bounds__(256) void flash_attn_kernel(
    const float* __restrict__ Q, const float* __restrict__ K,
    const float* __restrict__ V, float* __restrict__ O, int L)
{
    __shared__ float QsT[64*64];   // QsT[kk][qrow]
    __shared__ float KP [64*64];   // phase 1: KsT[kk][krow]; phase 2: Ps[qrow][krow]
    __shared__ float Vs [64*64];   // Vs[krow][dim]

    const int tid = threadIdx.x;
    const int tx = tid & 15, ty = tid >> 4;
    const int b = blockIdx.z, h = blockIdx.y, q0 = blockIdx.x * 64;

    const size_t base = ((size_t)b * L) * DMODEL + h * DHEAD;

    const int lr = tid >> 2;            // 0..63 loader row
    const int lc = (tid & 3) * 16;      // loader col segment

    {   // load Q tile, transposed
        const float* qp = Q + base + (size_t)(q0 + lr) * DMODEL + lc;
        #pragma unroll
        for (int j = 0; j < 4; j++) {
            float4 v = *(const float4*)(qp + 4*j);
            QsT[(lc+4*j+0)*64 + lr] = v.x;
            QsT[(lc+4*j+1)*64 + lr] = v.y;
            QsT[(lc+4*j+2)*64 + lr] = v.z;
            QsT[(lc+4*j+3)*64 + lr] = v.w;
        }
    }

    float m[4], l[4], acc[4][4];
    #pragma unroll
    for (int i = 0; i < 4; i++) {
        m[i] = -INFINITY; l[i] = 0.f;
        #pragma unroll
        for (int j = 0; j < 4; j++) acc[i][j] = 0.f;
    }

    const int ntiles = L / 64;
    for (int kt = 0; kt < ntiles; kt++) {
        __syncthreads();   // previous iteration's consumers done
        {   // load K (transposed) and V tiles
            const float* kp = K + base + (size_t)(kt*64 + lr) * DMODEL + lc;
            const float* vp = V + base + (size_t)(kt*64 + lr) * DMODEL + lc;
            #pragma unroll
            for (int j = 0; j < 4; j++) {
                float4 kv = *(const float4*)(kp + 4*j);
                KP[(lc+4*j+0)*64 + lr] = kv.x;
                KP[(lc+4*j+1)*64 + lr] = kv.y;
                KP[(lc+4*j+2)*64 + lr] = kv.z;
                KP[(lc+4*j+3)*64 + lr] = kv.w;
                *(float4*)&Vs[lr*64 + lc + 4*j] = *(const float4*)(vp + 4*j);
            }
        }
        __syncthreads();

        // S = Q @ K^T  (per-thread 4x4)
        float s[4][4];
        #pragma unroll
        for (int i = 0; i < 4; i++)
            #pragma unroll
            for (int j = 0; j < 4; j++) s[i][j] = 0.f;

        #pragma unroll 8
        for (int kk = 0; kk < 64; kk++) {
            float4 qv = *(const float4*)&QsT[kk*64 + 4*ty];
            float4 kv = *(const float4*)&KP [kk*64 + 4*tx];
            s[0][0] = fmaf(qv.x, kv.x, s[0][0]); s[0][1] = fmaf(qv.x, kv.y, s[0][1]);
            s[0][2] = fmaf(qv.x, kv.z, s[0][2]); s[0][3] = fmaf(qv.x, kv.w, s[0][3]);
            s[1][0] = fmaf(qv.y, kv.x, s[1][0]); s[1][1] = fmaf(qv.y, kv.y, s[1][1]);
            s[1][2] = fmaf(qv.y, kv.z, s[1][2]); s[1][3] = fmaf(qv.y, kv.w, s[1][3]);
            s[2][0] = fmaf(qv.z, kv.x, s[2][0]); s[2][1] = fmaf(qv.z, kv.y, s[2][1]);
            s[2][2] = fmaf(qv.z, kv.z, s[2][2]); s[2][3] = fmaf(qv.z, kv.w, s[2][3]);
            s[3][0] = fmaf(qv.w, kv.x, s[3][0]); s[3][1] = fmaf(qv.w, kv.y, s[3][1]);
            s[3][2] = fmaf(qv.w, kv.z, s[3][2]); s[3][3] = fmaf(qv.w, kv.w, s[3][3]);
        }

        __syncthreads();   // all KsT reads done; KP becomes Ps

        // online softmax (row stats shared across the 16 tx lanes via shfl)
        const float scale = 0.125f;   // 1/sqrt(64)
        #pragma unroll
        for (int i = 0; i < 4; i++) {
            float a0 = s[i][0]*scale, a1 = s[i][1]*scale;
            float a2 = s[i][2]*scale, a3 = s[i][3]*scale;
            float rm = fmaxf(fmaxf(a0, a1), fmaxf(a2, a3));
            rm = fmaxf(rm, __shfl_xor_sync(0xffffffffu, rm, 1));
            rm = fmaxf(rm, __shfl_xor_sync(0xffffffffu, rm, 2));
            rm = fmaxf(rm, __shfl_xor_sync(0xffffffffu, rm, 4));
            rm = fmaxf(rm, __shfl_xor_sync(0xffffffffu, rm, 8));
            float mnew = fmaxf(m[i], rm);
            float corr = __expf(m[i] - mnew);
            float p0 = __expf(a0 - mnew), p1 = __expf(a1 - mnew);
            float p2 = __expf(a2 - mnew), p3 = __expf(a3 - mnew);
            float rs = (p0 + p1) + (p2 + p3);
            rs += __shfl_xor_sync(0xffffffffu, rs, 1);
            rs += __shfl_xor_sync(0xffffffffu, rs, 2);
            rs += __shfl_xor_sync(0xffffffffu, rs, 4);
            rs += __shfl_xor_sync(0xffffffffu, rs, 8);
            l[i] = l[i]*corr + rs;
            m[i] = mnew;
            acc[i][0] *= corr; acc[i][1] *= corr;
            acc[i][2] *= corr; acc[i][3] *= corr;
            *(float4*)&KP[(4*ty + i)*64 + 4*tx] = make_float4(p0, p1, p2, p3);
        }
        __syncthreads();   // Ps visible

        // O += P @ V
        #pragma unroll 8
        for (int key = 0; key < 64; key++) {
            float4 vv = *(const float4*)&Vs[key*64 + 4*tx];
            #pragma unroll
            for (int i = 0; i < 4; i++) {
                float pv = KP[(4*ty + i)*64 + key];
                acc[i][0] = fmaf(pv, vv.x, acc[i][0]);
                acc[i][1] = fmaf(pv, vv.y, acc[i][1]);
                acc[i][2] = fmaf(pv, vv.z, acc[i][2]);
                acc[i][3] = fmaf(pv, vv.w, acc[i][3]);
            }
        }
    }

    #pragma unroll
    for (int i = 0; i < 4; i++) {
        float inv = 1.0f / l[i];
        float4 o = make_float4(acc[i][0]*inv, acc[i][1]*inv,
                               acc[i][2]*inv, acc[i][3]*inv);
        *(float4*)(O + base + (size_t)(q0 + 4*ty + i)*DMODEL + 4*tx) = o;
    }
}

// ------------------------------------------------------------ layernorm ----
__global__ __launch_bounds__(256) void ln_reduce(
    const float* __restrict__ a, const float* __restrict__ b,
    double* __restrict__ part)
{
    const int batch = blockIdx.y;
    const float* pa = a + (size_t)batch * NPER;
    const float* pb = b + (size_t)batch * NPER;
    double s = 0.0, ss = 0.0;
    for (int i = blockIdx.x*blockDim.x + threadIdx.x; i < NPER;
         i += gridDim.x*blockDim.x) {
        float z = pa[i] + pb[i];
        s += (double)z;
        ss += (double)z * (double)z;
    }
    __shared__ double sh[512];
    int tid = threadIdx.x;
    sh[tid] = s; sh[256 + tid] = ss;
    __syncthreads();
    for (int st = 128; st > 0; st >>= 1) {
        if (tid < st) { sh[tid] += sh[tid+st]; sh[256+tid] += sh[256+tid+st]; }
        __syncthreads();
    }
    if (tid == 0) {
        part[(batch*256 + blockIdx.x)*2 + 0] = sh[0];
        part[(batch*256 + blockIdx.x)*2 + 1] = sh[256];
    }
}

__global__ __launch_bounds__(256) void ln_stats(
    const double* __restrict__ part, float* __restrict__ stats)
{
    const int batch = blockIdx.x;
    int tid = threadIdx.x;
    __shared__ double sh[512];
    sh[tid]       = part[(batch*256 + tid)*2 + 0];
    sh[256 + tid] = part[(batch*256 + tid)*2 + 1];
    __syncthreads();
    for (int st = 128; st > 0; st >>= 1) {
        if (tid < st) { sh[tid] += sh[tid+st]; sh[256+tid] += sh[256+tid+st]; }
        __syncthreads();
    }
    if (tid == 0) {
        double mean = sh[0] / (double)NPER;
        double var  = sh[256] / (double)NPER - mean*mean + 1e-5;
        stats[batch*2 + 0] = (float)mean;
        stats[batch*2 + 1] = (float)(1.0 / sqrt(var));
    }
}

__global__ __launch_bounds__(256) void ln_apply(
    const float* __restrict__ a, const float* __restrict__ b,
    const float* __restrict__ stats, float* __restrict__ out)
{
    const int batch = blockIdx.y;
    const float mean = stats[batch*2 + 0];
    const float inv  = stats[batch*2 + 1];
    size_t off = (size_t)batch * NPER + (size_t)(blockIdx.x*blockDim.x + threadIdx.x)*4;
    float4 va = *(const float4*)(a + off);
    float4 vb = *(const float4*)(b + off);
    float4 o;
    o.x = (va.x + vb.x - mean) * inv;
    o.y = (va.y + vb.y - mean) * inv;
    o.z = (va.z + vb.z - mean) * inv;
    o.w = (va.w + vb.w - mean) * inv;
    *(float4*)(out + off) = o;
}

// -------------------------------------------------------------- launch -----
extern "C" void kernel_launch(void* const* d_in, const int* in_sizes, int n_in,
                              void* d_out, int out_size)
{
    const float* x  = (const float*)d_in[0];
    const float* wq = (const float*)d_in[1];
    const float* bq = (const float*)d_in[2];
    const float* wk = (const float*)d_in[3];
    const float* bk = (const float*)d_in[4];
    const float* wv = (const float*)d_in[5];
    const float* bv = (const float*)d_in[6];
    const float* w1 = (const float*)d_in[7];
    const float* b1 = (const float*)d_in[8];
    const float* w2 = (const float*)d_in[9];
    const float* b2 = (const float*)d_in[10];
    float* out = (float*)d_out;

    float *q, *k, *v, *attn, *h, *ff1, *ff2, *stats;
    double* part;
    cudaGetSymbolAddress((void**)&q,    g_q);
    cudaGetSymbolAddress((void**)&k,    g_k);
    cudaGetSymbolAddress((void**)&v,    g_v);
    cudaGetSymbolAddress((void**)&attn, g_attn);
    cudaGetSymbolAddress((void**)&h,    g_h);
    cudaGetSymbolAddress((void**)&ff1,  g_ff1);
    cudaGetSymbolAddress((void**)&ff2,  g_ff2);
    cudaGetSymbolAddress((void**)&part, g_part);
    cudaGetSymbolAddress((void**)&stats, g_stats);

    // QKV projections (tensor cores, tf32)
    dim3 gqkv(DMODEL/TBN, BL/TBM);
    tf32_gemm_bias<<<gqkv, 256>>>(x, wq, bq, q, BL, DMODEL, DMODEL, 0);
    tf32_gemm_bias<<<gqkv, 256>>>(x, wk, bk, k, BL, DMODEL, DMODEL, 0);
    tf32_gemm_bias<<<gqkv, 256>>>(x, wv, bv, v, BL, DMODEL, DMODEL, 0);

    // attention
    flash_attn_kernel<<<dim3(SEQLEN/64, NHEADS, BATCH), 256>>>(q, k, v, attn, SEQLEN);

    // residual + LN1 -> h
    ln_reduce<<<dim3(256, BATCH), 256>>>(x, attn, part);
    ln_stats <<<BATCH, 256>>>(part, stats);
    ln_apply <<<dim3(NPER/1024, BATCH), 256>>>(x, attn, stats, h);

    // FFN (tensor cores, tf32)
    tf32_gemm_bias<<<dim3(FFDIM/TBN,  BL/TBM), 256>>>(h,   w1, b1, ff1, BL, FFDIM,  DMODEL, 1);
    tf32_gemm_bias<<<dim3(DMODEL/TBN, BL/TBM), 256>>>(ff1, w2, b2, ff2, BL, DMODEL, FFDIM,  0);

    // residual + LN2 -> out
    ln_reduce<<<dim3(256, BATCH), 256>>>(h, ff2, part);
    ln_stats <<<BATCH, 256>>>(part, stats);
    ln_apply <<<dim3(NPER/1024, BATCH), 256>>>(h, ff2, stats, out);
}

// round 8
// speedup vs baseline: 2.6173x; 1.4808x over previous
#include <cuda_runtime.h>
#include <cstdint>
#include <math.h>

#define BATCH   2
#define SEQLEN  2048
#define DMODEL  1024
#define NHEADS  16
#define DHEAD   64
#define FFDIM   4096
#define BL      (BATCH*SEQLEN)          // 4096
#define NPER    (SEQLEN*DMODEL)        // per-batch layernorm size

// ---------------- scratch (static device globals; no allocation allowed) ----
__device__ float g_q   [BL*DMODEL];
__device__ float g_k   [BL*DMODEL];
__device__ float g_v   [BL*DMODEL];
__device__ float g_attn[BL*DMODEL];
__device__ float g_h   [BL*DMODEL];
__device__ float g_ff1 [BL*FFDIM];
__device__ float g_ff2 [BL*DMODEL];
__device__ double g_part[BATCH*256*2];
__device__ float  g_stats[BATCH*2];

// --------------------------------------------------------- tf32 helpers ----
__device__ __forceinline__ uint32_t f2tf32(float x) {
    uint32_t u;
    asm("cvt.rna.tf32.f32 %0, %1;" : "=r"(u) : "f"(x));
    return u;
}

__device__ __forceinline__ void mma_tf32(float* c, const uint32_t* a, const uint32_t* b) {
    asm volatile(
        "mma.sync.aligned.m16n8k8.row.col.f32.tf32.tf32.f32 "
        "{%0,%1,%2,%3}, {%4,%5,%6,%7}, {%8,%9}, {%0,%1,%2,%3};"
        : "+f"(c[0]), "+f"(c[1]), "+f"(c[2]), "+f"(c[3])
        : "r"(a[0]), "r"(a[1]), "r"(a[2]), "r"(a[3]), "r"(b[0]), "r"(b[1]));
}

// software 2^t on FMA/ALU pipes (avoids MUFU bottleneck). t <= 0 expected.
__device__ __forceinline__ float exp2s(float t) {
    t = fmaxf(t, -126.0f);
    float z = t + 12582912.0f;                    // round-to-int magic (1.5*2^23)
    int ni = __float_as_int(z) - 0x4B400000;
    float f = t - (z - 12582912.0f);              // f in [-0.5, 0.5]
    float p = 1.3333558e-3f;
    p = fmaf(p, f, 9.6181291e-3f);
    p = fmaf(p, f, 5.5504109e-2f);
    p = fmaf(p, f, 2.4022651e-1f);
    p = fmaf(p, f, 6.9314718e-1f);
    p = fmaf(p, f, 1.0f);
    return p * __int_as_float((ni + 127) << 23);
}

// ------------------------------------------------------------- tf32 GEMM ----
// C[M,N] = A[M,K] @ W[K,N] + bias (+relu). Tensor cores via mma.sync tf32.
#define TBM 128
#define TBN 128
#define TBK 16
#define ASTRIDE 20     // A smem [m][k] stride: (20*q + r) mod 32 covers all banks
#define WSTRIDE 136    // W smem [k][n] stride: bank = 8r + q, conflict-free

__global__ __launch_bounds__(256) void tf32_gemm_bias(
    const float* __restrict__ A, const float* __restrict__ W,
    const float* __restrict__ bias, float* __restrict__ C,
    int M, int N, int K, int relu)
{
    __shared__ uint32_t As[2][TBM*ASTRIDE];   // [m][k] tf32 bits
    __shared__ uint32_t Ws[2][TBK*WSTRIDE];   // [k][n] tf32 bits

    const int tid  = threadIdx.x;
    const int lane = tid & 31;
    const int warp = tid >> 5;
    const int q = lane >> 2, r = lane & 3;
    const int wr = warp >> 2, wc = warp & 3;
    const int bm = blockIdx.y * TBM, bn = blockIdx.x * TBN;

    const int arow = tid >> 2;
    const int akc  = (tid & 3) * 4;
    const int wrow = tid >> 5;
    const int wcol = (tid & 31) * 4;

    const float* Ag = A + (size_t)(bm + arow) * K + akc;
    const float* Wg = W + (size_t)wrow * N + bn + wcol;

    float acc[4][4][4];
    #pragma unroll
    for (int i = 0; i < 4; i++)
        #pragma unroll
        for (int j = 0; j < 4; j++)
            #pragma unroll
            for (int e = 0; e < 4; e++) acc[i][j][e] = 0.f;

    float4 ra0, ra1, rw0, rw1;

    ra0 = *(const float4*)Ag;
    ra1 = *(const float4*)(Ag + (size_t)64 * K);
    rw0 = *(const float4*)Wg;
    rw1 = *(const float4*)(Wg + (size_t)8 * N);
    Ag += TBK;
    Wg += (size_t)TBK * N;
    {
        uint4 pa0 = make_uint4(f2tf32(ra0.x), f2tf32(ra0.y), f2tf32(ra0.z), f2tf32(ra0.w));
        uint4 pa1 = make_uint4(f2tf32(ra1.x), f2tf32(ra1.y), f2tf32(ra1.z), f2tf32(ra1.w));
        uint4 pw0 = make_uint4(f2tf32(rw0.x), f2tf32(rw0.y), f2tf32(rw0.z), f2tf32(rw0.w));
        uint4 pw1 = make_uint4(f2tf32(rw1.x), f2tf32(rw1.y), f2tf32(rw1.z), f2tf32(rw1.w));
        *(uint4*)&As[0][arow*ASTRIDE + akc]        = pa0;
        *(uint4*)&As[0][(arow + 64)*ASTRIDE + akc] = pa1;
        *(uint4*)&Ws[0][wrow*WSTRIDE + wcol]       = pw0;
        *(uint4*)&Ws[0][(wrow + 8)*WSTRIDE + wcol] = pw1;
    }
    __syncthreads();

    const int nchunk = K / TBK;
    #pragma unroll 1
    for (int c = 0; c < nchunk; c++) {
        const int cur = c & 1;
        const bool has_next = (c + 1 < nchunk);

        if (has_next) {
            ra0 = *(const float4*)Ag;
            ra1 = *(const float4*)(Ag + (size_t)64 * K);
            rw0 = *(const float4*)Wg;
            rw1 = *(const float4*)(Wg + (size_t)8 * N);
            Ag += TBK;
            Wg += (size_t)TBK * N;
        }

        #pragma unroll
        for (int k8 = 0; k8 < TBK; k8 += 8) {
            uint32_t af[4][4], bf[4][2];
            #pragma unroll
            for (int tm = 0; tm < 4; tm++) {
                const int m = wr*64 + tm*16 + q;
                af[tm][0] = As[cur][m*ASTRIDE + k8 + r];
                af[tm][1] = As[cur][(m + 8)*ASTRIDE + k8 + r];
                af[tm][2] = As[cur][m*ASTRIDE + k8 + r + 4];
                af[tm][3] = As[cur][(m + 8)*ASTRIDE + k8 + r + 4];
            }
            #pragma unroll
            for (int tn = 0; tn < 4; tn++) {
                const int n = wc*32 + tn*8 + q;
                bf[tn][0] = Ws[cur][(k8 + r)*WSTRIDE + n];
                bf[tn][1] = Ws[cur][(k8 + r + 4)*WSTRIDE + n];
            }
            #pragma unroll
            for (int tm = 0; tm < 4; tm++)
                #pragma unroll
                for (int tn = 0; tn < 4; tn++)
                    mma_tf32(acc[tm][tn], af[tm], bf[tn]);
        }

        if (has_next) {
            const int nxt = cur ^ 1;
            uint4 pa0 = make_uint4(f2tf32(ra0.x), f2tf32(ra0.y), f2tf32(ra0.z), f2tf32(ra0.w));
            uint4 pa1 = make_uint4(f2tf32(ra1.x), f2tf32(ra1.y), f2tf32(ra1.z), f2tf32(ra1.w));
            uint4 pw0 = make_uint4(f2tf32(rw0.x), f2tf32(rw0.y), f2tf32(rw0.z), f2tf32(rw0.w));
            uint4 pw1 = make_uint4(f2tf32(rw1.x), f2tf32(rw1.y), f2tf32(rw1.z), f2tf32(rw1.w));
            *(uint4*)&As[nxt][arow*ASTRIDE + akc]        = pa0;
            *(uint4*)&As[nxt][(arow + 64)*ASTRIDE + akc] = pa1;
            *(uint4*)&Ws[nxt][wrow*WSTRIDE + wcol]       = pw0;
            *(uint4*)&Ws[nxt][(wrow + 8)*WSTRIDE + wcol] = pw1;
        }
        __syncthreads();
    }

    #pragma unroll
    for (int tm = 0; tm < 4; tm++) {
        const int row = bm + wr*64 + tm*16 + q;
        #pragma unroll
        for (int tn = 0; tn < 4; tn++) {
            const int col = bn + wc*32 + tn*8 + 2*r;
            const float2 bv = *(const float2*)(bias + col);
            float2 c01, c23;
            c01.x = acc[tm][tn][0] + bv.x; c01.y = acc[tm][tn][1] + bv.y;
            c23.x = acc[tm][tn][2] + bv.x; c23.y = acc[tm][tn][3] + bv.y;
            if (relu) {
                c01.x = fmaxf(c01.x, 0.f); c01.y = fmaxf(c01.y, 0.f);
                c23.x = fmaxf(c23.x, 0.f); c23.y = fmaxf(c23.y, 0.f);
            }
            *(float2*)(C + (size_t)row*N + col)       = c01;
            *(float2*)(C + (size_t)(row + 8)*N + col) = c23;
        }
    }
}

// --------------------------------------- tensor-core flash attention -------
// Br=128 q-rows per block, Bc=32 keys per tile, dh=64. 256 threads / 8 warps.
// Warp w owns q-rows 16w..16w+15 (m16n8k8 fragment rows). Q frags in regs.
// Softmax in log2 domain with software exp2 (no MUFU).
#define FA_BR 128
#define FA_BC 32
#define PS_STRIDE 36    // [qrow][key]: A-frag read bank = 4q + r, conflict-free
#define KS_STRIDE 40    // [dh][key]:   B-frag read bank = 8r + q, conflict-free
#define VS_STRIDE 72    // [key][dh]:   B-frag read bank = 8r + q, conflict-free

__global__ __launch_bounds__(256) void flash_attn_tc(
    const float* __restrict__ Q, const float* __restrict__ K,
    const float* __restrict__ V, float* __restrict__ O)
{
    __shared__ uint32_t KsT[64*KS_STRIDE];       // 10240 B
    __shared__ uint32_t Vs [FA_BC*VS_STRIDE];    //  9216 B
    __shared__ uint32_t Ps [FA_BR*PS_STRIDE];    // 18432 B

    const int tid  = threadIdx.x;
    const int lane = tid & 31;
    const int warp = tid >> 5;
    const int qg = lane >> 2, r = lane & 3;
    const int b = blockIdx.z, h = blockIdx.y;
    const int q0 = blockIdx.x * FA_BR;
    const size_t base = ((size_t)b * SEQLEN) * DMODEL + h * DHEAD;

    const int mrow = warp*16 + qg;               // fragment row (and +8)

    // Q fragments straight from gmem (once per block)
    uint32_t qf[8][4];
    {
        const float* qp  = Q + base + (size_t)(q0 + mrow) * DMODEL;
        const float* qp8 = qp + (size_t)8 * DMODEL;
        #pragma unroll
        for (int ks = 0; ks < 8; ks++) {
            qf[ks][0] = f2tf32(__ldg(qp  + ks*8 + r));
            qf[ks][1] = f2tf32(__ldg(qp8 + ks*8 + r));
            qf[ks][2] = f2tf32(__ldg(qp  + ks*8 + r + 4));
            qf[ks][3] = f2tf32(__ldg(qp8 + ks*8 + r + 4));
        }
    }

    float oc[8][4];
    #pragma unroll
    for (int nf = 0; nf < 8; nf++)
        #pragma unroll
        for (int e = 0; e < 4; e++) oc[nf][e] = 0.f;
    float m0 = -INFINITY, m1 = -INFINITY, l0 = 0.f, l1 = 0.f;

    // loader mappings
    const int vrow = tid >> 3;          // 0..31 (key)
    const int vc0  = (tid & 7) * 4;     // dh col

    const float SCL = 0.125f * 1.44269504f;   // 1/sqrt(dh) * log2(e)

    for (int kt = 0; kt < SEQLEN/FA_BC; kt++) {
        __syncthreads();   // K/V (and cross-warp) consumers of prev tile done
        {   // K tile -> KsT[dh][key] (transposed, tf32). key = lane, dh = warp*8..+7
            const float* kp = K + base + (size_t)(kt*FA_BC + lane)*DMODEL + warp*8;
            float4 k0 = *(const float4*)kp;
            float4 k1 = *(const float4*)(kp + 4);
            KsT[(warp*8+0)*KS_STRIDE + lane] = f2tf32(k0.x);
            KsT[(warp*8+1)*KS_STRIDE + lane] = f2tf32(k0.y);
            KsT[(warp*8+2)*KS_STRIDE + lane] = f2tf32(k0.z);
            KsT[(warp*8+3)*KS_STRIDE + lane] = f2tf32(k0.w);
            KsT[(warp*8+4)*KS_STRIDE + lane] = f2tf32(k1.x);
            KsT[(warp*8+5)*KS_STRIDE + lane] = f2tf32(k1.y);
            KsT[(warp*8+6)*KS_STRIDE + lane] = f2tf32(k1.z);
            KsT[(warp*8+7)*KS_STRIDE + lane] = f2tf32(k1.w);
            // V tile -> Vs[key][dh] (natural, tf32)
            const float* vp = V + base + (size_t)(kt*FA_BC + vrow)*DMODEL + vc0;
            float4 v0 = *(const float4*)vp;
            float4 v1 = *(const float4*)(vp + 32);
            *(uint4*)&Vs[vrow*VS_STRIDE + vc0] =
                make_uint4(f2tf32(v0.x), f2tf32(v0.y), f2tf32(v0.z), f2tf32(v0.w));
            *(uint4*)&Vs[vrow*VS_STRIDE + vc0 + 32] =
                make_uint4(f2tf32(v1.x), f2tf32(v1.y), f2tf32(v1.z), f2tf32(v1.w));
        }
        __syncthreads();

        // S = Q @ K^T : 8 k-steps (dh) x 4 n-frags (keys)
        float sc[4][4];
        #pragma unroll
        for (int nf = 0; nf < 4; nf++)
            #pragma unroll
            for (int e = 0; e < 4; e++) sc[nf][e] = 0.f;

        #pragma unroll
        for (int ks = 0; ks < 8; ks++) {
            uint32_t bf[4][2];
            #pragma unroll
            for (int nf = 0; nf < 4; nf++) {
                bf[nf][0] = KsT[(ks*8 + r)*KS_STRIDE + nf*8 + qg];
                bf[nf][1] = KsT[(ks*8 + r + 4)*KS_STRIDE + nf*8 + qg];
            }
            #pragma unroll
            for (int nf = 0; nf < 4; nf++)
                mma_tf32(sc[nf], qf[ks], bf[nf]);
        }

        // online softmax in log2 domain (software exp2, no MUFU)
        float rm0 = -INFINITY, rm1 = -INFINITY;
        #pragma unroll
        for (int nf = 0; nf < 4; nf++) {
            rm0 = fmaxf(rm0, fmaxf(sc[nf][0], sc[nf][1]));
            rm1 = fmaxf(rm1, fmaxf(sc[nf][2], sc[nf][3]));
        }
        rm0 = fmaxf(rm0, __shfl_xor_sync(0xffffffffu, rm0, 1));
        rm0 = fmaxf(rm0, __shfl_xor_sync(0xffffffffu, rm0, 2));
        rm1 = fmaxf(rm1, __shfl_xor_sync(0xffffffffu, rm1, 1));
        rm1 = fmaxf(rm1, __shfl_xor_sync(0xffffffffu, rm1, 2));

        const float mt0 = fmaxf(m0, rm0 * SCL);
        const float mt1 = fmaxf(m1, rm1 * SCL);
        const float c0 = exp2s(m0 - mt0);
        const float c1 = exp2s(m1 - mt1);
        m0 = mt0; m1 = mt1;

        float rs0 = 0.f, rs1 = 0.f;
        #pragma unroll
        for (int nf = 0; nf < 4; nf++) {
            const float p0 = exp2s(fmaf(sc[nf][0], SCL, -mt0));
            const float p1 = exp2s(fmaf(sc[nf][1], SCL, -mt0));
            const float p2 = exp2s(fmaf(sc[nf][2], SCL, -mt1));
            const float p3 = exp2s(fmaf(sc[nf][3], SCL, -mt1));
            rs0 += p0 + p1;
            rs1 += p2 + p3;
            const int colw = nf*8 + 2*r;
            *(uint2*)&Ps[(mrow)*PS_STRIDE + colw]     = make_uint2(f2tf32(p0), f2tf32(p1));
            *(uint2*)&Ps[(mrow + 8)*PS_STRIDE + colw] = make_uint2(f2tf32(p2), f2tf32(p3));
        }
        rs0 += __shfl_xor_sync(0xffffffffu, rs0, 1);
        rs0 += __shfl_xor_sync(0xffffffffu, rs0, 2);
        rs1 += __shfl_xor_sync(0xffffffffu, rs1, 1);
        rs1 += __shfl_xor_sync(0xffffffffu, rs1, 2);
        l0 = l0*c0 + rs0;
        l1 = l1*c1 + rs1;

        #pragma unroll
        for (int nf = 0; nf < 8; nf++) {
            oc[nf][0] *= c0; oc[nf][1] *= c0;
            oc[nf][2] *= c1; oc[nf][3] *= c1;
        }
        __syncwarp();     // P visible to own warp (P rows are warp-private)

        // O += P @ V : 4 k-steps (keys) x 8 n-frags (dh)
        #pragma unroll
        for (int ks = 0; ks < 4; ks++) {
            uint32_t af[4];
            af[0] = Ps[(mrow)*PS_STRIDE     + ks*8 + r];
            af[1] = Ps[(mrow + 8)*PS_STRIDE + ks*8 + r];
            af[2] = Ps[(mrow)*PS_STRIDE     + ks*8 + r + 4];
            af[3] = Ps[(mrow + 8)*PS_STRIDE + ks*8 + r + 4];
            #pragma unroll
            for (int nf = 0; nf < 8; nf++) {
                uint32_t bf2[2];
                bf2[0] = Vs[(ks*8 + r)*VS_STRIDE + nf*8 + qg];
                bf2[1] = Vs[(ks*8 + r + 4)*VS_STRIDE + nf*8 + qg];
                mma_tf32(oc[nf], af, bf2);
            }
        }
    }

    // write O (normalize by l)
    const float inv0 = 1.0f / l0;
    const float inv1 = 1.0f / l1;
    float* op  = O + base + (size_t)(q0 + mrow) * DMODEL;
    float* op8 = op + (size_t)8 * DMODEL;
    #pragma unroll
    for (int nf = 0; nf < 8; nf++) {
        const int col = nf*8 + 2*r;
        *(float2*)(op  + col) = make_float2(oc[nf][0]*inv0, oc[nf][1]*inv0);
        *(float2*)(op8 + col) = make_float2(oc[nf][2]*inv1, oc[nf][3]*inv1);
    }
}

// ------------------------------------------------------------ layernorm ----
__global__ __launch_bounds__(256) void ln_reduce(
    const float* __restrict__ a, const float* __restrict__ b,
    double* __restrict__ part)
{
    const int batch = blockIdx.y;
    const float* pa = a + (size_t)batch * NPER;
    const float* pb = b + (size_t)batch * NPER;
    double s = 0.0, ss = 0.0;
    for (int i = blockIdx.x*blockDim.x + threadIdx.x; i < NPER;
         i += gridDim.x*blockDim.x) {
        float z = pa[i] + pb[i];
        s += (double)z;
        ss += (double)z * (double)z;
    }
    __shared__ double sh[512];
    int tid = threadIdx.x;
    sh[tid] = s; sh[256 + tid] = ss;
    __syncthreads();
    for (int st = 128; st > 0; st >>= 1) {
        if (tid < st) { sh[tid] += sh[tid+st]; sh[256+tid] += sh[256+tid+st]; }
        __syncthreads();
    }
    if (tid == 0) {
        part[(batch*256 + blockIdx.x)*2 + 0] = sh[0];
        part[(batch*256 + blockIdx.x)*2 + 1] = sh[256];
    }
}

__global__ __launch_bounds__(256) void ln_stats(
    const double* __restrict__ part, float* __restrict__ stats)
{
    const int batch = blockIdx.x;
    int tid = threadIdx.x;
    __shared__ double sh[512];
    sh[tid]       = part[(batch*256 + tid)*2 + 0];
    sh[256 + tid] = part[(batch*256 + tid)*2 + 1];
    __syncthreads();
    for (int st = 128; st > 0; st >>= 1) {
        if (tid < st) { sh[tid] += sh[tid+st]; sh[256+tid] += sh[256+tid+st]; }
        __syncthreads();
    }
    if (tid == 0) {
        double mean = sh[0] / (double)NPER;
        double var  = sh[256] / (double)NPER - mean*mean + 1e-5;
        stats[batch*2 + 0] = (float)mean;
        stats[batch*2 + 1] = (float)(1.0 / sqrt(var));
    }
}

__global__ __launch_bounds__(256) void ln_apply(
    const float* __restrict__ a, const float* __restrict__ b,
    const float* __restrict__ stats, float* __restrict__ out)
{
    const int batch = blockIdx.y;
    const float mean = stats[batch*2 + 0];
    const float inv  = stats[batch*2 + 1];
    size_t off = (size_t)batch * NPER + (size_t)(blockIdx.x*blockDim.x + threadIdx.x)*4;
    float4 va = *(const float4*)(a + off);
    float4 vb = *(const float4*)(b + off);
    float4 o;
    o.x = (va.x + vb.x - mean) * inv;
    o.y = (va.y + vb.y - mean) * inv;
    o.z = (va.z + vb.z - mean) * inv;
    o.w = (va.w + vb.w - mean) * inv;
    *(float4*)(out + off) = o;
}

// -------------------------------------------------------------- launch -----
extern "C" void kernel_launch(void* const* d_in, const int* in_sizes, int n_in,
                              void* d_out, int out_size)
{
    const float* x  = (const float*)d_in[0];
    const float* wq = (const float*)d_in[1];
    const float* bq = (const float*)d_in[2];
    const float* wk = (const float*)d_in[3];
    const float* bk = (const float*)d_in[4];
    const float* wv = (const float*)d_in[5];
    const float* bv = (const float*)d_in[6];
    const float* w1 = (const float*)d_in[7];
    const float* b1 = (const float*)d_in[8];
    const float* w2 = (const float*)d_in[9];
    const float* b2 = (const float*)d_in[10];
    float* out = (float*)d_out;

    float *q, *k, *v, *attn, *h, *ff1, *ff2, *stats;
    double* part;
    cudaGetSymbolAddress((void**)&q,    g_q);
    cudaGetSymbolAddress((void**)&k,    g_k);
    cudaGetSymbolAddress((void**)&v,    g_v);
    cudaGetSymbolAddress((void**)&attn, g_attn);
    cudaGetSymbolAddress((void**)&h,    g_h);
    cudaGetSymbolAddress((void**)&ff1,  g_ff1);
    cudaGetSymbolAddress((void**)&ff2,  g_ff2);
    cudaGetSymbolAddress((void**)&part, g_part);
    cudaGetSymbolAddress((void**)&stats, g_stats);

    // QKV projections (tensor cores, tf32)
    dim3 gqkv(DMODEL/TBN, BL/TBM);
    tf32_gemm_bias<<<gqkv, 256>>>(x, wq, bq, q, BL, DMODEL, DMODEL, 0);
    tf32_gemm_bias<<<gqkv, 256>>>(x, wk, bk, k, BL, DMODEL, DMODEL, 0);
    tf32_gemm_bias<<<gqkv, 256>>>(x, wv, bv, v, BL, DMODEL, DMODEL, 0);

    // attention (tensor cores + software exp2)
    flash_attn_tc<<<dim3(SEQLEN/FA_BR, NHEADS, BATCH), 256>>>(q, k, v, attn);

    // residual + LN1 -> h
    ln_reduce<<<dim3(256, BATCH), 256>>>(x, attn, part);
    ln_stats <<<BATCH, 256>>>(part, stats);
    ln_apply <<<dim3(NPER/1024, BATCH), 256>>>(x, attn, stats, h);

    // FFN (tensor cores, tf32)
    tf32_gemm_bias<<<dim3(FFDIM/TBN,  BL/TBM), 256>>>(h,   w1, b1, ff1, BL, FFDIM,  DMODEL, 1);
    tf32_gemm_bias<<<dim3(DMODEL/TBN, BL/TBM), 256>>>(ff1, w2, b2, ff2, BL, DMODEL, FFDIM,  0);

    // residual + LN2 -> out
    ln_reduce<<<dim3(256, BATCH), 256>>>(h, ff2, part);
    ln_stats <<<BATCH, 256>>>(part, stats);
    ln_apply <<<dim3(NPER/1024, BATCH), 256>>>(h, ff2, stats, out);
}